// round 16
// baseline (speedup 1.0000x reference)
#include <cuda_runtime.h>

#define NF    32
#define NDOF  29
#define BLK   96            // 2 compute warps (64 batches, 1 thread/batch) + 1 flush warp
#define NB    64            // batches per block
#define TS    28            // slab floats per batch per chunk: 2 frames * 12 + 4 pad

__global__ void __launch_bounds__(BLK, 8)
fk_kernel(const float* __restrict__ ja,        // [B, 29]
          const float* __restrict__ axes,      // [32, 3]
          const float* __restrict__ origins,   // [32, 4, 4]
          const float* __restrict__ mmult,     // [2]
          const float* __restrict__ moff,      // [2]
          const int*   __restrict__ ctrl,      // [29]
          const int*   __restrict__ msrc,      // [2]
          const int*   __restrict__ mdst,      // [2]
          const int*   __restrict__ types,     // [32]
          float*       __restrict__ out,       // [B, 32, 4, 4]
          int Bn)
{
    // Per (frame, row j 0..2) constants, 3 x float4:
    //   cA = (O_j.xyz, O_j.w)
    //   cB = (O_j x k [revolute], O_j.k [prismatic])
    //   cC = ((O_j.k)k - O_j.xyz [revolute], 0)
    // L_j.xyz = cA + sn*cB + (1-cs)*cC ;  L_j.w = a*cB.w + cA.w
    __shared__ __align__(16) float4 s_cst[NF * 9];         // 4.5 KB
    __shared__ float4 s_meta[NF];                          // (src bits, mul, off, 0)
    __shared__ float  s_raw[NB * NDOF];                    // 7.4 KB
    __shared__ __align__(16) float s_slab[2][NB * TS];     // 14 KB double buffer

    const int tid  = threadIdx.x;
    const int lane = tid & 31;
    const int wid  = tid >> 5;          // 0,1 = compute; 2 = flush
    const int b0   = blockIdx.x * NB;

    // ---- per-frame meta: unified (src, mul, off) => angle = fmaf(raw[src],mul,off) ----
    if (tid < NF) {
        const int f = tid;
        int slot = -1;
        for (int j = 0; j < NDOF; ++j) if (ctrl[j] == f) slot = j;
        int src = 0; float mul = 0.f, off = 0.f;
        if (slot >= 0) { src = slot; mul = 1.f; off = 0.f; }
        else {
            for (int m = 0; m < 2; ++m) {
                if (mdst[m] == f) {
                    const int sf = msrc[m];
                    for (int j = 0; j < NDOF; ++j) if (ctrl[j] == sf) src = j;
                    mul = mmult[m]; off = moff[m];
                }
            }
        }
        s_meta[f] = make_float4(__int_as_float(src), mul, off, 0.f);
    }

    // ---- per (frame,row) constants: 96 entries, 96 threads ----
    for (int i = tid; i < NF * 3; i += BLK) {
        const int f  = i / 3;
        const int rr = i - f * 3;
        const float4 orow = *reinterpret_cast<const float4*>(origins + f * 16 + rr * 4);
        const float kx = axes[f * 3 + 0], ky = axes[f * 3 + 1], kz = axes[f * 3 + 2];
        const int   ty = types[f];
        const float vr = orow.x * kx + orow.y * ky + orow.z * kz;
        float bx = 0.f, by = 0.f, bz = 0.f, cx = 0.f, cy = 0.f, cz = 0.f, ve = 0.f;
        if (ty == 1) {
            bx = orow.y * kz - orow.z * ky;
            by = orow.z * kx - orow.x * kz;
            bz = orow.x * ky - orow.y * kx;
            cx = fmaf(vr, kx, -orow.x);
            cy = fmaf(vr, ky, -orow.y);
            cz = fmaf(vr, kz, -orow.z);
        } else if (ty == 2) {
            ve = vr;
        }
        s_cst[(f * 3 + rr) * 3 + 0] = make_float4(orow.x, orow.y, orow.z, orow.w);
        s_cst[(f * 3 + rr) * 3 + 1] = make_float4(bx, by, bz, ve);
        s_cst[(f * 3 + rr) * 3 + 2] = make_float4(cx, cy, cz, 0.f);
    }

    // ---- stage raw joint angles (coalesced) ----
    for (int i = tid; i < NB * NDOF; i += BLK) {
        const int bb = i / NDOF;
        s_raw[i] = (b0 + bb < Bn) ? ja[(size_t)b0 * NDOF + i] : 0.f;
    }
    __syncthreads();

    float4* const out4 = reinterpret_cast<float4*>(out);

    // compute-role state (allocated on compute path only)
    float P[12], Q[12];
    #pragma unroll
    for (int j = 0; j < 12; ++j) { P[j] = 0.f; Q[j] = 0.f; }
    P[0] = 1.f; P[5] = 1.f; P[10] = 1.f;

    // ---- pipelined mainloop: compute stages chunk c while flush drains chunk c-1 ----
    #pragma unroll
    for (int c = 0; c < NF / 2; ++c) {
        if (wid < 2) {
            // ===== compute role: this thread owns batch tid (0..63) =====
            float* buf = s_slab[c & 1] + tid * TS;
            #pragma unroll
            for (int ff = 0; ff < 2; ++ff) {
                const int f = c * 2 + ff;
                // build local transform L
                const float4 mt = s_meta[f];
                const float  a  = fmaf(s_raw[tid * NDOF + __float_as_int(mt.x)], mt.y, mt.z);
                const float sn = __sinf(a);
                const float cs = __cosf(a);
                const float C  = 1.f - cs;
                const float4* cf = s_cst + f * 9;
                float L[12];
                #pragma unroll
                for (int j = 0; j < 3; ++j) {
                    const float4 cA = cf[j * 3 + 0];
                    const float4 cB = cf[j * 3 + 1];
                    const float4 cC = cf[j * 3 + 2];
                    L[j * 4 + 0] = fmaf(C, cC.x, fmaf(sn, cB.x, cA.x));
                    L[j * 4 + 1] = fmaf(C, cC.y, fmaf(sn, cB.y, cA.y));
                    L[j * 4 + 2] = fmaf(C, cC.z, fmaf(sn, cB.z, cA.z));
                    L[j * 4 + 3] = fmaf(a, cB.w, cA.w);
                }
                // chain update
                if (f >= 30) {
                    #pragma unroll
                    for (int j = 0; j < 12; ++j) P[j] = Q[j];
                }
                #pragma unroll
                for (int rr = 0; rr < 3; ++rr) {
                    const float p0 = P[rr * 4 + 0], p1 = P[rr * 4 + 1];
                    const float p2 = P[rr * 4 + 2], p3 = P[rr * 4 + 3];
                    P[rr * 4 + 0] = fmaf(p0, L[0], fmaf(p1, L[4], p2 * L[8]));
                    P[rr * 4 + 1] = fmaf(p0, L[1], fmaf(p1, L[5], p2 * L[9]));
                    P[rr * 4 + 2] = fmaf(p0, L[2], fmaf(p1, L[6], p2 * L[10]));
                    P[rr * 4 + 3] = fmaf(p0, L[3], fmaf(p1, L[7], fmaf(p2, L[11], p3)));
                }
                if (f == 10) {
                    #pragma unroll
                    for (int j = 0; j < 12; ++j) Q[j] = P[j];
                }
                // stage
                float4* sp = reinterpret_cast<float4*>(buf + ff * 12);
                sp[0] = make_float4(P[0], P[1], P[2],  P[3]);
                sp[1] = make_float4(P[4], P[5], P[6],  P[7]);
                sp[2] = make_float4(P[8], P[9], P[10], P[11]);
            }
        } else if (c > 0) {
            // ===== flush role: drain chunk c-1 =====
            const float* buf = s_slab[(c - 1) & 1];
            #pragma unroll
            for (int it = 0; it < 16; ++it) {
                const int v = it * 32 + lane;
                const int b = v >> 3;               // batch within block (0..63)
                const int w = v & 7;                // frame*4 + row within chunk
                const int fi = w >> 2;
                const int rr = w & 3;
                float4 val;
                if (rr < 3) val = *reinterpret_cast<const float4*>(buf + b * TS + fi * 12 + rr * 4);
                else        val = make_float4(0.f, 0.f, 0.f, 1.f);
                const int gb = b0 + b;
                if (gb < Bn)
                    __stcs(&out4[(size_t)gb * (NF * 4) + (size_t)(c - 1) * 8 + w], val);
            }
        }
        __syncthreads();
    }

    // ---- final flush: chunk 15 ----
    if (wid == 2) {
        const float* buf = s_slab[(NF / 2 - 1) & 1];
        #pragma unroll
        for (int it = 0; it < 16; ++it) {
            const int v = it * 32 + lane;
            const int b = v >> 3;
            const int w = v & 7;
            const int fi = w >> 2;
            const int rr = w & 3;
            float4 val;
            if (rr < 3) val = *reinterpret_cast<const float4*>(buf + b * TS + fi * 12 + rr * 4);
            else        val = make_float4(0.f, 0.f, 0.f, 1.f);
            const int gb = b0 + b;
            if (gb < Bn)
                __stcs(&out4[(size_t)gb * (NF * 4) + (size_t)(NF / 2 - 1) * 8 + w], val);
        }
    }
}

extern "C" void kernel_launch(void* const* d_in, const int* in_sizes, int n_in,
                              void* d_out, int out_size) {
    const float* ja      = (const float*)d_in[0];
    const float* axes    = (const float*)d_in[1];
    const float* origins = (const float*)d_in[2];
    const float* mm      = (const float*)d_in[3];
    const float* mo      = (const float*)d_in[4];
    const int*   ctrl    = (const int*)d_in[5];
    const int*   msrc    = (const int*)d_in[6];
    const int*   mdst    = (const int*)d_in[7];
    const int*   types   = (const int*)d_in[8];
    float*       out     = (float*)d_out;

    const int Bn   = in_sizes[0] / NDOF;
    const int grid = (Bn + NB - 1) / NB;
    fk_kernel<<<grid, BLK>>>(ja, axes, origins, mm, mo, ctrl, msrc, mdst, types, out, Bn);
}

// round 17
// speedup vs baseline: 1.0703x; 1.0703x over previous
#include <cuda_runtime.h>

#define NF    32
#define NDOF  29
#define BLK   64            // 64 batches per block, 1 thread per batch, 2 warps
#define TS    52            // slab floats per batch: 4 frames * 12 + 4 pad

__global__ void __launch_bounds__(BLK, 7)
fk_kernel(const float* __restrict__ ja,        // [B, 29]
          const float* __restrict__ axes,      // [32, 3]
          const float* __restrict__ origins,   // [32, 4, 4]
          const float* __restrict__ mmult,     // [2]
          const float* __restrict__ moff,      // [2]
          const int*   __restrict__ ctrl,      // [29]
          const int*   __restrict__ msrc,      // [2]
          const int*   __restrict__ mdst,      // [2]
          const int*   __restrict__ types,     // [32]
          float*       __restrict__ out,       // [B, 32, 4, 4]
          int Bn)
{
    // Per (frame, row j 0..2) constants, 3 x float4:
    //   cA = (O_j.xyz, O_j.w)
    //   cB = (O_j x k [revolute], O_j.k [prismatic])
    //   cC = ((O_j.k)k - O_j.xyz [revolute], 0)
    // L_j.xyz = cA + sn*cB + (1-cs)*cC ;  L_j.w = a*cB.w + cA.w
    __shared__ __align__(16) float4 s_cst[NF * 9];     // 4.5 KB
    __shared__ float4 s_meta[NF];                      // (src bits, mul, off, 0)
    __shared__ float  s_raw[BLK * NDOF];               // 7.4 KB
    __shared__ __align__(16) float s_slab[BLK * TS];   // 13.3 KB (warp-private halves)

    const int tid  = threadIdx.x;
    const int lane = tid & 31;
    const int wid  = tid >> 5;
    const int b0   = blockIdx.x * BLK;

    // ---- per-frame meta: unified (src, mul, off) => angle = fmaf(raw[src],mul,off) ----
    if (tid < NF) {
        const int f = tid;
        int slot = -1;
        for (int j = 0; j < NDOF; ++j) if (ctrl[j] == f) slot = j;
        int src = 0; float mul = 0.f, off = 0.f;
        if (slot >= 0) { src = slot; mul = 1.f; off = 0.f; }
        else {
            for (int m = 0; m < 2; ++m) {
                if (mdst[m] == f) {
                    const int sf = msrc[m];
                    for (int j = 0; j < NDOF; ++j) if (ctrl[j] == sf) src = j;
                    mul = mmult[m]; off = moff[m];
                }
            }
        }
        s_meta[f] = make_float4(__int_as_float(src), mul, off, 0.f);
    }

    // ---- per (frame,row) constants ----
    for (int i = tid; i < NF * 3; i += BLK) {
        const int f  = i / 3;
        const int rr = i - f * 3;
        const float4 orow = *reinterpret_cast<const float4*>(origins + f * 16 + rr * 4);
        const float kx = axes[f * 3 + 0], ky = axes[f * 3 + 1], kz = axes[f * 3 + 2];
        const int   ty = types[f];
        const float vr = orow.x * kx + orow.y * ky + orow.z * kz;
        float bx = 0.f, by = 0.f, bz = 0.f, cx = 0.f, cy = 0.f, cz = 0.f, ve = 0.f;
        if (ty == 1) {
            bx = orow.y * kz - orow.z * ky;
            by = orow.z * kx - orow.x * kz;
            bz = orow.x * ky - orow.y * kx;
            cx = fmaf(vr, kx, -orow.x);
            cy = fmaf(vr, ky, -orow.y);
            cz = fmaf(vr, kz, -orow.z);
        } else if (ty == 2) {
            ve = vr;
        }
        s_cst[(f * 3 + rr) * 3 + 0] = make_float4(orow.x, orow.y, orow.z, orow.w);
        s_cst[(f * 3 + rr) * 3 + 1] = make_float4(bx, by, bz, ve);
        s_cst[(f * 3 + rr) * 3 + 2] = make_float4(cx, cy, cz, 0.f);
    }

    // ---- stage raw joint angles (coalesced) ----
    for (int i = tid; i < BLK * NDOF; i += BLK) {
        const int bb = i / NDOF;
        s_raw[i] = (b0 + bb < Bn) ? ja[(size_t)b0 * NDOF + i] : 0.f;
    }
    __syncthreads();

    // ---- main chain: 2-frame compute sub-chunks, 4-frame flush cadence ----
    float P[12];
    #pragma unroll
    for (int j = 0; j < 12; ++j) P[j] = 0.f;
    P[0] = 1.f; P[5] = 1.f; P[10] = 1.f;
    float Q[12];
    #pragma unroll
    for (int j = 0; j < 12; ++j) Q[j] = 0.f;

    float* const wslab = s_slab + wid * (32 * TS);
    float4* const out4 = reinterpret_cast<float4*>(out);

    #pragma unroll
    for (int sc = 0; sc < NF / 4; ++sc) {
        // -- two 2-frame compute sub-chunks (phase-split for ILP) --
        #pragma unroll
        for (int pp = 0; pp < 2; ++pp) {
            // phase A: build 2 independent local transforms
            float L[2][12];
            #pragma unroll
            for (int ff = 0; ff < 2; ++ff) {
                const int f = sc * 4 + pp * 2 + ff;
                const float4 mt = s_meta[f];
                const float  a  = fmaf(s_raw[tid * NDOF + __float_as_int(mt.x)], mt.y, mt.z);
                const float sn = __sinf(a);
                const float cs = __cosf(a);
                const float C  = 1.f - cs;
                const float4* cf = s_cst + f * 9;
                #pragma unroll
                for (int j = 0; j < 3; ++j) {
                    const float4 cA = cf[j * 3 + 0];
                    const float4 cB = cf[j * 3 + 1];
                    const float4 cC = cf[j * 3 + 2];
                    L[ff][j * 4 + 0] = fmaf(C, cC.x, fmaf(sn, cB.x, cA.x));
                    L[ff][j * 4 + 1] = fmaf(C, cC.y, fmaf(sn, cB.y, cA.y));
                    L[ff][j * 4 + 2] = fmaf(C, cC.z, fmaf(sn, cB.z, cA.z));
                    L[ff][j * 4 + 3] = fmaf(a, cB.w, cA.w);
                }
            }
            // phase B: serial chain updates + stage
            #pragma unroll
            for (int ff = 0; ff < 2; ++ff) {
                const int f = sc * 4 + pp * 2 + ff;
                if (f >= 30) {
                    #pragma unroll
                    for (int j = 0; j < 12; ++j) P[j] = Q[j];
                }
                #pragma unroll
                for (int rr = 0; rr < 3; ++rr) {
                    const float p0 = P[rr * 4 + 0], p1 = P[rr * 4 + 1];
                    const float p2 = P[rr * 4 + 2], p3 = P[rr * 4 + 3];
                    P[rr * 4 + 0] = fmaf(p0, L[ff][0], fmaf(p1, L[ff][4], p2 * L[ff][8]));
                    P[rr * 4 + 1] = fmaf(p0, L[ff][1], fmaf(p1, L[ff][5], p2 * L[ff][9]));
                    P[rr * 4 + 2] = fmaf(p0, L[ff][2], fmaf(p1, L[ff][6], p2 * L[ff][10]));
                    P[rr * 4 + 3] = fmaf(p0, L[ff][3], fmaf(p1, L[ff][7], fmaf(p2, L[ff][11], p3)));
                }
                if (f == 10) {
                    #pragma unroll
                    for (int j = 0; j < 12; ++j) Q[j] = P[j];
                }
                float4* sp = reinterpret_cast<float4*>(wslab + lane * TS + (pp * 2 + ff) * 12);
                sp[0] = make_float4(P[0], P[1], P[2],  P[3]);
                sp[1] = make_float4(P[4], P[5], P[6],  P[7]);
                sp[2] = make_float4(P[8], P[9], P[10], P[11]);
            }
        }

        __syncwarp();

        // -- flush 4 frames: each iter = 2 batches x 256 B contiguous, streaming --
        #pragma unroll
        for (int it = 0; it < 16; ++it) {
            const int v = it * 32 + lane;
            const int b = v >> 4;               // warp-local batch (0..31)
            const int w = v & 15;               // frame*4 + row within 4-frame chunk
            const int fi = w >> 2;
            const int rr = w & 3;
            float4 val;
            if (rr < 3) val = *reinterpret_cast<const float4*>(wslab + b * TS + fi * 12 + rr * 4);
            else        val = make_float4(0.f, 0.f, 0.f, 1.f);
            const int gbat = b0 + (wid << 5) + b;
            if (gbat < Bn)
                __stcs(&out4[(size_t)gbat * (NF * 4) + sc * 16 + w], val);
        }

        __syncwarp();
    }
}

extern "C" void kernel_launch(void* const* d_in, const int* in_sizes, int n_in,
                              void* d_out, int out_size) {
    const float* ja      = (const float*)d_in[0];
    const float* axes    = (const float*)d_in[1];
    const float* origins = (const float*)d_in[2];
    const float* mm      = (const float*)d_in[3];
    const float* mo      = (const float*)d_in[4];
    const int*   ctrl    = (const int*)d_in[5];
    const int*   msrc    = (const int*)d_in[6];
    const int*   mdst    = (const int*)d_in[7];
    const int*   types   = (const int*)d_in[8];
    float*       out     = (float*)d_out;

    const int Bn   = in_sizes[0] / NDOF;
    const int grid = (Bn + BLK - 1) / BLK;
    fk_kernel<<<grid, BLK>>>(ja, axes, origins, mm, mo, ctrl, msrc, mdst, types, out, Bn);
}